// round 8
// baseline (speedup 1.0000x reference)
#include <cuda_runtime.h>
#include <cuda_fp16.h>
#include <math.h>
#include <stdint.h>

#define NN   100000
#define NE   250000
#define NB   2000
#define FIN  75
#define DIM  32
#define HID  128
#define NOUT 1024           // DIM*DIM
#define MPAD 250112         // 1954 * 128

// ---------------- scratch (static __device__, no allocation) ----------------
__device__ __align__(16) __half g_ewb[(size_t)MPAD * NOUT];  // edge weights fp16, [o][i] per edge
__device__ __align__(16) __half g_w2b[NOUT * HID];           // W2 fp16, column-permuted (c' = o*32+i)
__device__ float g_b2p[NOUT];                                // b2 permuted
__device__ float g_x[NN * DIM];                 // node state
__device__ float g_acc[NN * DIM];               // conv scatter accumulator
__device__ int   g_cnt[NN];                     // in-degree
__device__ int   g_goff[NB + 1];                // graph offsets (graph_index is sorted)
__device__ float g_h2[NB * DIM];                // set2set LSTM h
__device__ float g_c2[NB * DIM];                // set2set LSTM c
__device__ float g_qstar[NB * 2 * DIM];         // set2set q_star
// transposed weights
__device__ float g_w0T[FIN * DIM];
__device__ float g_w1T[11 * HID];
__device__ float g_wihT[DIM * 96];
__device__ float g_whhT[DIM * 96];
__device__ float g_lwihT[64 * 128];
__device__ float g_lwhhT[DIM * 128];

__device__ __forceinline__ uint32_t smem_u32(const void* p) {
    uint32_t a;
    asm("{ .reg .u64 t; cvta.to.shared.u64 t, %1; cvt.u32.u64 %0, t; }" : "=r"(a) : "l"(p));
    return a;
}

// ---------------- prep: transposes + fp16 W2 with column permutation ----------------
__global__ void prep_kernel(const float* __restrict__ w0, const float* __restrict__ w1,
                            const float* __restrict__ gwih, const float* __restrict__ gwhh,
                            const float* __restrict__ lwih, const float* __restrict__ lwhh,
                            const float* __restrict__ w2, const float* __restrict__ b2) {
    int t = blockIdx.x * 256 + threadIdx.x;
    if (t < FIN * DIM) { int i = t / DIM, o = t % DIM; g_w0T[t] = w0[o * FIN + i]; }
    if (t < 11 * HID)  { int i = t / HID, j = t % HID; g_w1T[t] = w1[j * 11 + i]; }
    if (t < DIM * 96)  { int i = t / 96,  r = t % 96;  g_wihT[t] = gwih[r * DIM + i]; g_whhT[t] = gwhh[r * DIM + i]; }
    if (t < 64 * 128)  { int i = t / 128, r = t % 128; g_lwihT[t] = lwih[r * 64 + i]; }
    if (t < DIM * 128) { int i = t / 128, r = t % 128; g_lwhhT[t] = lwhh[r * DIM + i]; }
    if (t < NOUT) { int corig = (t & 31) * 32 + (t >> 5); g_b2p[t] = b2[corig]; }
    if (t < NOUT * HID) {
        int cp = t / HID, k = t % HID;
        int corig = (cp & 31) * 32 + (cp >> 5);      // cp = o*32+i holds original column i*32+o
        g_w2b[t] = __float2half(w2[corig * HID + k]);
    }
}

__global__ void zero_cnt_kernel() {
    int i = blockIdx.x * 256 + threadIdx.x;
    if (i < NN) g_cnt[i] = 0;
}
__global__ void deg_kernel(const int* __restrict__ ei) {
    int e = blockIdx.x * 256 + threadIdx.x;
    if (e < NE) atomicAdd(&g_cnt[ei[NE + e]], 1);
}

__global__ void goff_kernel(const int* __restrict__ gidx) {
    int g = blockIdx.x * 256 + threadIdx.x;
    if (g > NB) return;
    int lo = 0, hi = NN;
    while (lo < hi) { int mid = (lo + hi) >> 1; if (gidx[mid] < g) lo = mid + 1; else hi = mid; }
    g_goff[g] = lo;
}

// ---------------- lin0: x = relu(nf @ W0^T + b) ----------------
__global__ void lin0_kernel(const float* __restrict__ nf, const float* __restrict__ b) {
    int warp = threadIdx.x >> 5;
    int node = blockIdx.x * 8 + warp;
    int o = threadIdx.x & 31;
    __shared__ float sf[8][FIN + 1];
    int base = blockIdx.x * 8;
    for (int idx = threadIdx.x; idx < 8 * FIN; idx += 256) {
        int nn = base + idx / FIN;
        sf[idx / FIN][idx % FIN] = (nn < NN) ? nf[(size_t)nn * FIN + idx % FIN] : 0.f;
    }
    __syncthreads();
    if (node >= NN) return;
    float acc = b[o];
#pragma unroll
    for (int i = 0; i < FIN; i++) acc = fmaf(sf[warp][i], g_w0T[i * DIM + o], acc);
    g_x[node * DIM + o] = fmaxf(acc, 0.f);
}

__global__ void zero_acc_kernel() {
    int i = blockIdx.x * 256 + threadIdx.x;
    if (i < NN * DIM) g_acc[i] = 0.f;
}

// ---- fused GEMM + conv-iter-1: per CTA of 128 edges ----
// prologue: hw tile in smem; gather x[src] (fp16) + dst indices
// per slab: HMMA -> stage C -> write ewb -> accumulate iter-1 messages from staged smem
#define SM_A     0
#define SM_B     32768
#define SM_CSTG  65536                    // 128 x 272B
#define SM_SEF   65536                    // prologue overlap: 128 x 12 floats
#define SM_W1T   (65536 + 6144)
#define SM_B1    (65536 + 6144 + 5632)
#define SM_BIAS  100352                   // 1024 floats
#define SM_XS    104448                   // 128 x 32 fp16 = 8192
#define SM_DST   112640                   // 128 ints
#define SMEM_GEMM_TOTAL 113152
#define CSTRIDE 272

__device__ __forceinline__ void mma_fp16(float* c, const uint32_t* a, uint32_t b0, uint32_t b1) {
    asm volatile(
        "mma.sync.aligned.m16n8k16.row.col.f32.f16.f16.f32 "
        "{%0,%1,%2,%3}, {%4,%5,%6,%7}, {%8,%9}, {%0,%1,%2,%3};"
        : "+f"(c[0]), "+f"(c[1]), "+f"(c[2]), "+f"(c[3])
        : "r"(a[0]), "r"(a[1]), "r"(a[2]), "r"(a[3]), "r"(b0), "r"(b1));
}

__global__ void __launch_bounds__(256) gemm_fused_kernel(const float* __restrict__ ef,
                                                         const float* __restrict__ b1,
                                                         const int* __restrict__ ei) {
    extern __shared__ __align__(16) char smem[];
    uint32_t sbase = smem_u32(smem);
    float* sef   = (float*)(smem + SM_SEF);
    float* sw1t  = (float*)(smem + SM_W1T);
    float* sb1   = (float*)(smem + SM_B1);
    float* sbias = (float*)(smem + SM_BIAS);
    __half* sxs  = (__half*)(smem + SM_XS);
    int*   sdst  = (int*)(smem + SM_DST);
    int tid = threadIdx.x, lane = tid & 31, wid = tid >> 5;
    int e0 = blockIdx.x * 128;

    // ---- prologue loads ----
    for (int idx = tid; idx < 128 * 11; idx += 256) {
        int r = idx / 11, i = idx % 11;
        int e = e0 + r;
        sef[r * 12 + i] = (e < NE) ? ef[(size_t)e * 11 + i] : 0.f;
    }
    for (int idx = tid; idx < 11 * HID; idx += 256) sw1t[idx] = g_w1T[idx];
    if (tid < 128) sb1[tid] = b1[tid];
#pragma unroll
    for (int l = 0; l < 4; l++) sbias[tid + l * 256] = g_b2p[tid + l * 256];
    if (tid < 128) {
        int e = e0 + tid;
        sdst[tid] = (e < NE) ? ei[NE + e] : -1;
    }
    // gather x[src] for conv-iter-1 (fp16)
    for (int idx = tid; idx < 128 * 32; idx += 256) {
        int r = idx >> 5, i = idx & 31;
        int e = e0 + r;
        float xv = (e < NE) ? g_x[ei[e] * DIM + i] : 0.f;
        sxs[idx] = __float2half(xv);
    }
    __syncthreads();

    // ---- build A tile: hw = relu(ef @ W1^T + b1), fp16, xor-swizzled ----
#pragma unroll
    for (int ci = 0; ci < 8; ci++) {
        int cidx = tid + ci * 256;
        int row = cidx >> 4, c = cidx & 15;
        int k0 = c * 8;
        float v[8];
#pragma unroll
        for (int j = 0; j < 8; j++) v[j] = sb1[k0 + j];
#pragma unroll
        for (int i = 0; i < 11; i++) {
            float e_ = sef[row * 12 + i];
#pragma unroll
            for (int j = 0; j < 8; j++) v[j] = fmaf(e_, sw1t[i * HID + k0 + j], v[j]);
        }
        uint32_t p[4];
#pragma unroll
        for (int j = 0; j < 4; j++) {
            __half2 h = __floats2half2_rn(fmaxf(v[2 * j], 0.f), fmaxf(v[2 * j + 1], 0.f));
            p[j] = *(uint32_t*)&h;
        }
        int cs = (c & 8) | ((c ^ row) & 7);
        *(uint4*)(smem + SM_A + row * 256 + cs * 16) = make_uint4(p[0], p[1], p[2], p[3]);
    }
    __syncthreads();

    int wm = (wid & 3) * 32;
    int wn = (wid >> 2) * 64;
    int mrow = tid & 127;          // msg row (edge within CTA)
    int og0 = tid >> 7;            // 0 or 1; handles og0 and og0+2
    int mdst = sdst[mrow];

    for (int nb = 0; nb < 8; nb++) {
        const uint4* gB = (const uint4*)(g_w2b + (size_t)(nb * 128) * HID);
#pragma unroll
        for (int it = 0; it < 8; it++) {
            int idx = tid + it * 256;
            int row = idx >> 4, c = idx & 15;
            uint4 v = gB[idx];
            int cs = (c & 8) | ((c ^ row) & 7);
            *(uint4*)(smem + SM_B + row * 256 + cs * 16) = v;
        }
        __syncthreads();

        float acc[2][8][4];
#pragma unroll
        for (int mb = 0; mb < 2; mb++)
#pragma unroll
            for (int nbb = 0; nbb < 8; nbb++)
#pragma unroll
                for (int q = 0; q < 4; q++) acc[mb][nbb][q] = 0.f;

#pragma unroll
        for (int ks = 0; ks < 8; ks++) {
            int ck0 = ks * 2;
            uint32_t a[2][4], b[4][4];
#pragma unroll
            for (int mb = 0; mb < 2; mb++) {
                int row = wm + mb * 16 + (lane & 7) + ((lane >> 3) & 1) * 8;
                int ck = ck0 + (lane >> 4);
                int cs = (ck & 8) | ((ck ^ row) & 7);
                uint32_t addr = sbase + SM_A + row * 256 + cs * 16;
                asm volatile("ldmatrix.sync.aligned.m8n8.x4.shared.b16 {%0,%1,%2,%3}, [%4];"
                             : "=r"(a[mb][0]), "=r"(a[mb][1]), "=r"(a[mb][2]), "=r"(a[mb][3])
                             : "r"(addr));
            }
#pragma unroll
            for (int nb4 = 0; nb4 < 4; nb4++) {
                int t = lane >> 3, r = lane & 7;
                int n = wn + nb4 * 16 + r + (t >> 1) * 8;
                int ck = ck0 + (t & 1);
                int cs = (ck & 8) | ((ck ^ n) & 7);
                uint32_t addr = sbase + SM_B + n * 256 + cs * 16;
                asm volatile("ldmatrix.sync.aligned.m8n8.x4.shared.b16 {%0,%1,%2,%3}, [%4];"
                             : "=r"(b[nb4][0]), "=r"(b[nb4][1]), "=r"(b[nb4][2]), "=r"(b[nb4][3])
                             : "r"(addr));
            }
#pragma unroll
            for (int mb = 0; mb < 2; mb++)
#pragma unroll
                for (int nbb = 0; nbb < 8; nbb++)
                    mma_fp16(acc[mb][nbb], a[mb], b[nbb >> 1][(nbb & 1) * 2], b[nbb >> 1][(nbb & 1) * 2 + 1]);
        }
        __syncthreads();

        int g = lane >> 2, tg = lane & 3;
#pragma unroll
        for (int mb = 0; mb < 2; mb++)
#pragma unroll
            for (int nbb = 0; nbb < 8; nbb++) {
                int rowl = wm + mb * 16 + g;
                int nl = wn + nbb * 8 + tg * 2;
                float bb0 = sbias[nb * 128 + nl], bb1 = sbias[nb * 128 + nl + 1];
                float* c = acc[mb][nbb];
                __half2 p0 = __floats2half2_rn(c[0] + bb0, c[1] + bb1);
                __half2 p1 = __floats2half2_rn(c[2] + bb0, c[3] + bb1);
                *(uint32_t*)(smem + SM_CSTG + rowl * CSTRIDE + nl * 2) = *(uint32_t*)&p0;
                *(uint32_t*)(smem + SM_CSTG + (rowl + 8) * CSTRIDE + nl * 2) = *(uint32_t*)&p1;
            }
        __syncthreads();

        // coalesced write of this 128-column slab
        __half* dst = g_ewb + (size_t)e0 * NOUT + nb * 128;
#pragma unroll
        for (int it = 0; it < 8; it++) {
            int idx = tid + it * 256;
            int row = idx >> 4, c = idx & 15;
            uint4 v = *(const uint4*)(smem + SM_CSTG + row * CSTRIDE + c * 16);
            *(uint4*)(dst + (size_t)row * NOUT + c * 8) = v;
        }

        // conv-iter-1 partial messages from the staged slab
        // slab local col c = og*32 + i, output o = nb*4 + og
        if (mdst >= 0) {
            const __half2* xs = (const __half2*)(sxs + mrow * 32);
#pragma unroll
            for (int t2 = 0; t2 < 2; t2++) {
                int og = og0 + t2 * 2;
                const __half2* sp = (const __half2*)(smem + SM_CSTG + mrow * CSTRIDE + og * 64);
                float macc = 0.f;
#pragma unroll
                for (int i2 = 0; i2 < 16; i2++) {
                    float2 xp = __half22float2(xs[i2]);
                    float2 wp = __half22float2(sp[i2]);
                    macc = fmaf(xp.x, wp.x, fmaf(xp.y, wp.y, macc));
                }
                atomicAdd(&g_acc[mdst * DIM + nb * 4 + og], macc);
            }
        }
        __syncthreads();
    }
}

// ---------------- NNConv: warp per edge, lane = output channel, [o][i] vectorized loads ----------------
__global__ void conv_kernel(const int* __restrict__ ei) {
    int e = blockIdx.x * 8 + (threadIdx.x >> 5);
    if (e >= NE) return;
    int o = threadIdx.x & 31;
    int src = ei[e];
    int dst = ei[NE + e];
    float xv = g_x[src * DIM + o];
    const uint4* w = (const uint4*)(g_ewb + (size_t)e * NOUT + o * 32);
    uint4 w0 = w[0], w1 = w[1], w2 = w[2], w3 = w[3];
    uint32_t ws[16] = {w0.x, w0.y, w0.z, w0.w, w1.x, w1.y, w1.z, w1.w,
                       w2.x, w2.y, w2.z, w2.w, w3.x, w3.y, w3.z, w3.w};
    float acc = 0.f;
#pragma unroll
    for (int i = 0; i < 16; i++) {
        float2 wp = __half22float2(*(__half2*)&ws[i]);
        float x0 = __shfl_sync(0xffffffffu, xv, 2 * i);
        float x1 = __shfl_sync(0xffffffffu, xv, 2 * i + 1);
        acc = fmaf(x0, wp.x, fmaf(x1, wp.y, acc));
    }
    atomicAdd(&g_acc[dst * DIM + o], acc);
}

// ---------------- scatter-mean + relu + GRU (in-place on g_x); zeroes g_acc after read ----------------
__global__ void gru_kernel(const float* __restrict__ cbias, const float* __restrict__ bih,
                           const float* __restrict__ bhh) {
    int warp = threadIdx.x >> 5;
    int node = blockIdx.x * 8 + warp;
    int o = threadIdx.x & 31;
    __shared__ float sm[8][DIM], sh[8][DIM];
    if (node < NN) {
        int c = g_cnt[node]; if (c < 1) c = 1;
        sm[warp][o] = fmaxf(g_acc[node * DIM + o] / (float)c + cbias[o], 0.f);
        sh[warp][o] = g_x[node * DIM + o];
        g_acc[node * DIM + o] = 0.f;   // ready for next conv iteration
    }
    __syncthreads();
    if (node >= NN) return;
    float gir = bih[o], giz = bih[DIM + o], gin = bih[2 * DIM + o];
    float ghr = bhh[o], ghz = bhh[DIM + o], ghn = bhh[2 * DIM + o];
#pragma unroll
    for (int i = 0; i < DIM; i++) {
        float mi = sm[warp][i], hi = sh[warp][i];
        gir = fmaf(mi, g_wihT[i * 96 + o], gir);
        giz = fmaf(mi, g_wihT[i * 96 + DIM + o], giz);
        gin = fmaf(mi, g_wihT[i * 96 + 2 * DIM + o], gin);
        ghr = fmaf(hi, g_whhT[i * 96 + o], ghr);
        ghz = fmaf(hi, g_whhT[i * 96 + DIM + o], ghz);
        ghn = fmaf(hi, g_whhT[i * 96 + 2 * DIM + o], ghn);
    }
    float r = 1.f / (1.f + expf(-(gir + ghr)));
    float z = 1.f / (1.f + expf(-(giz + ghz)));
    float nv = tanhf(gin + r * ghn);
    g_x[node * DIM + o] = (1.f - z) * nv + z * sh[warp][o];
}

__global__ void zero_s2s_kernel() {
    int i = blockIdx.x * 256 + threadIdx.x;
    if (i < NB * DIM) { g_h2[i] = 0.f; g_c2[i] = 0.f; }
    if (i < NB * 2 * DIM) g_qstar[i] = 0.f;
}

// ---------------- Set2Set LSTM cell ----------------
__global__ void lstm_kernel(const float* __restrict__ bih, const float* __restrict__ bhh) {
    int warp = threadIdx.x >> 5;
    int b = blockIdx.x * 8 + warp;
    int o = threadIdx.x & 31;
    __shared__ float sq[8][64], shh[8][DIM];
    if (b < NB) {
        sq[warp][o]      = g_qstar[b * 64 + o];
        sq[warp][32 + o] = g_qstar[b * 64 + 32 + o];
        shh[warp][o]     = g_h2[b * DIM + o];
    }
    __syncthreads();
    if (b >= NB) return;
    float gi = bih[o] + bhh[o];
    float gf = bih[32 + o] + bhh[32 + o];
    float gg = bih[64 + o] + bhh[64 + o];
    float go = bih[96 + o] + bhh[96 + o];
#pragma unroll
    for (int i = 0; i < 64; i++) {
        float v = sq[warp][i];
        gi = fmaf(v, g_lwihT[i * 128 + o], gi);
        gf = fmaf(v, g_lwihT[i * 128 + 32 + o], gf);
        gg = fmaf(v, g_lwihT[i * 128 + 64 + o], gg);
        go = fmaf(v, g_lwihT[i * 128 + 96 + o], go);
    }
#pragma unroll
    for (int i = 0; i < DIM; i++) {
        float v = shh[warp][i];
        gi = fmaf(v, g_lwhhT[i * 128 + o], gi);
        gf = fmaf(v, g_lwhhT[i * 128 + 32 + o], gf);
        gg = fmaf(v, g_lwhhT[i * 128 + 64 + o], gg);
        go = fmaf(v, g_lwhhT[i * 128 + 96 + o], go);
    }
    float si = 1.f / (1.f + expf(-gi));
    float sf = 1.f / (1.f + expf(-gf));
    float so = 1.f / (1.f + expf(-go));
    float cc = sf * g_c2[b * DIM + o] + si * tanhf(gg);
    g_c2[b * DIM + o] = cc;
    g_h2[b * DIM + o] = so * tanhf(cc);
}

// ---------------- Set2Set attention: one block per graph ----------------
__global__ void attn_kernel() {
    int g = blockIdx.x;
    int s = g_goff[g], e = g_goff[g + 1];
    int lane = threadIdx.x & 31, w = threadIdx.x >> 5;
    __shared__ float q[DIM];
    __shared__ float red[4];
    __shared__ float sr[4][DIM];
    __shared__ float sd[4];
    if (threadIdx.x < DIM) q[threadIdx.x] = g_h2[g * DIM + threadIdx.x];
    __syncthreads();
    float mx = -INFINITY;
    for (int n = s + w; n < e; n += 4) {
        float v = g_x[n * DIM + lane] * q[lane];
#pragma unroll
        for (int off = 16; off; off >>= 1) v += __shfl_xor_sync(0xffffffffu, v, off);
        mx = fmaxf(mx, v);
    }
    if (lane == 0) red[w] = mx;
    __syncthreads();
    mx = fmaxf(fmaxf(red[0], red[1]), fmaxf(red[2], red[3]));
    float denom = 0.f, racc = 0.f;
    for (int n = s + w; n < e; n += 4) {
        float xo = g_x[n * DIM + lane];
        float v = xo * q[lane];
#pragma unroll
        for (int off = 16; off; off >>= 1) v += __shfl_xor_sync(0xffffffffu, v, off);
        float ex = __expf(v - mx);
        denom += ex;
        racc = fmaf(ex, xo, racc);
    }
    sr[w][lane] = racc;
    if (lane == 0) sd[w] = denom;
    __syncthreads();
    if (w == 0) {
        float r = sr[0][lane] + sr[1][lane] + sr[2][lane] + sr[3][lane];
        float d = sd[0] + sd[1] + sd[2] + sd[3];
        r = (d > 0.f) ? r / d : 0.f;
        g_qstar[g * 64 + lane] = q[lane];
        g_qstar[g * 64 + 32 + lane] = r;
    }
}

// ---------------- writeout: [pooled (2000x64), out (100000x32)] ----------------
__global__ void writeout_kernel(float* __restrict__ out) {
    int i = blockIdx.x * 256 + threadIdx.x;
    if (i >= NB * 64 + NN * DIM) return;
    out[i] = (i < NB * 64) ? g_qstar[i] : g_x[i - NB * 64];
}

// ---------------- launch ----------------
extern "C" void kernel_launch(void* const* d_in, const int* in_sizes, int n_in,
                              void* d_out, int out_size) {
    const float* nf        = (const float*)d_in[0];
    const float* ef        = (const float*)d_in[1];
    const float* lin0_w    = (const float*)d_in[2];
    const float* lin0_b    = (const float*)d_in[3];
    const float* nn_w1     = (const float*)d_in[4];
    const float* nn_b1     = (const float*)d_in[5];
    const float* nn_w2     = (const float*)d_in[6];
    const float* nn_b2     = (const float*)d_in[7];
    const float* conv_bias = (const float*)d_in[8];
    const float* gru_wih   = (const float*)d_in[9];
    const float* gru_whh   = (const float*)d_in[10];
    const float* gru_bih   = (const float*)d_in[11];
    const float* gru_bhh   = (const float*)d_in[12];
    const float* lstm_wih  = (const float*)d_in[13];
    const float* lstm_whh  = (const float*)d_in[14];
    const float* lstm_bih  = (const float*)d_in[15];
    const float* lstm_bhh  = (const float*)d_in[16];
    const int*   ei        = (const int*)d_in[17];
    const int*   gidx      = (const int*)d_in[18];

    static int smem_set = 0;
    if (!smem_set) {
        cudaFuncSetAttribute(gemm_fused_kernel, cudaFuncAttributeMaxDynamicSharedMemorySize,
                             SMEM_GEMM_TOTAL);
        smem_set = 1;
    }

    prep_kernel<<<512, 256>>>(lin0_w, nn_w1, gru_wih, gru_whh, lstm_wih, lstm_whh, nn_w2, nn_b2);
    zero_cnt_kernel<<<(NN + 255) / 256, 256>>>();
    deg_kernel<<<(NE + 255) / 256, 256>>>(ei);
    goff_kernel<<<8, 256>>>(gidx);
    lin0_kernel<<<NN / 8, 256>>>(nf, lin0_b);
    zero_acc_kernel<<<(NN * DIM + 255) / 256, 256>>>();
    gemm_fused_kernel<<<MPAD / 128, 256, SMEM_GEMM_TOTAL>>>(ef, nn_b1, ei);   // includes conv iter 1

    gru_kernel<<<NN / 8, 256>>>(conv_bias, gru_bih, gru_bhh);                  // iter 1 GRU
    for (int t = 0; t < 2; t++) {                                              // iters 2,3
        conv_kernel<<<NE / 8, 256>>>(ei);
        gru_kernel<<<NN / 8, 256>>>(conv_bias, gru_bih, gru_bhh);
    }

    zero_s2s_kernel<<<(NB * 2 * DIM + 255) / 256, 256>>>();
    for (int s = 0; s < 3; s++) {
        lstm_kernel<<<NB / 8, 256>>>(lstm_bih, lstm_bhh);
        attn_kernel<<<NB, 128>>>();
    }
    writeout_kernel<<<(NB * 64 + NN * DIM + 255) / 256, 256>>>((float*)d_out);
}

// round 9
// speedup vs baseline: 1.0286x; 1.0286x over previous
#include <cuda_runtime.h>
#include <cuda_fp16.h>
#include <math.h>
#include <stdint.h>

#define NN   100000
#define NE   250000
#define NB   2000
#define FIN  75
#define DIM  32
#define HID  128
#define NOUT 1024           // DIM*DIM
#define MPAD 250112         // 1954 * 128

// ---------------- scratch (static __device__, no allocation) ----------------
__device__ __align__(16) __half g_ewb[(size_t)MPAD * NOUT];  // edge weights fp16, [o][i] per edge
__device__ __align__(16) __half g_w2b[NOUT * HID];           // W2 fp16, column-permuted (c' = o*32+i)
__device__ float g_b2p[NOUT];                                // b2 permuted
__device__ float g_x[NN * DIM];                 // node state
__device__ float g_acc[NN * DIM];               // conv scatter accumulator
__device__ int   g_cnt[NN];                     // in-degree
__device__ int   g_goff[NB + 1];                // graph offsets (graph_index is sorted)
__device__ float g_h2[NB * DIM];                // set2set LSTM h
__device__ float g_c2[NB * DIM];                // set2set LSTM c
__device__ float g_qstar[NB * 2 * DIM];         // set2set q_star
// transposed weights
__device__ float g_w0T[FIN * DIM];
__device__ float g_w1T[11 * HID];
__device__ float g_wihT[DIM * 96];
__device__ float g_whhT[DIM * 96];
__device__ float g_lwihT[64 * 128];
__device__ float g_lwhhT[DIM * 128];

__device__ __forceinline__ uint32_t smem_u32(const void* p) {
    uint32_t a;
    asm("{ .reg .u64 t; cvta.to.shared.u64 t, %1; cvt.u32.u64 %0, t; }" : "=r"(a) : "l"(p));
    return a;
}

// ---------------- prep: transposes + fp16 W2 with column permutation ----------------
__global__ void prep_kernel(const float* __restrict__ w0, const float* __restrict__ w1,
                            const float* __restrict__ gwih, const float* __restrict__ gwhh,
                            const float* __restrict__ lwih, const float* __restrict__ lwhh,
                            const float* __restrict__ w2, const float* __restrict__ b2) {
    int t = blockIdx.x * 256 + threadIdx.x;
    if (t < FIN * DIM) { int i = t / DIM, o = t % DIM; g_w0T[t] = w0[o * FIN + i]; }
    if (t < 11 * HID)  { int i = t / HID, j = t % HID; g_w1T[t] = w1[j * 11 + i]; }
    if (t < DIM * 96)  { int i = t / 96,  r = t % 96;  g_wihT[t] = gwih[r * DIM + i]; g_whhT[t] = gwhh[r * DIM + i]; }
    if (t < 64 * 128)  { int i = t / 128, r = t % 128; g_lwihT[t] = lwih[r * 64 + i]; }
    if (t < DIM * 128) { int i = t / 128, r = t % 128; g_lwhhT[t] = lwhh[r * DIM + i]; }
    if (t < NOUT) { int corig = (t & 31) * 32 + (t >> 5); g_b2p[t] = b2[corig]; }
    if (t < NOUT * HID) {
        int cp = t / HID, k = t % HID;
        int corig = (cp & 31) * 32 + (cp >> 5);      // cp = o*32+i holds original column i*32+o
        g_w2b[t] = __float2half(w2[corig * HID + k]);
    }
}

__global__ void zero_cnt_kernel() {
    int i = blockIdx.x * 256 + threadIdx.x;
    if (i < NN) g_cnt[i] = 0;
}
__global__ void deg_kernel(const int* __restrict__ ei) {
    int e = blockIdx.x * 256 + threadIdx.x;
    if (e < NE) atomicAdd(&g_cnt[ei[NE + e]], 1);
}

__global__ void goff_kernel(const int* __restrict__ gidx) {
    int g = blockIdx.x * 256 + threadIdx.x;
    if (g > NB) return;
    int lo = 0, hi = NN;
    while (lo < hi) { int mid = (lo + hi) >> 1; if (gidx[mid] < g) lo = mid + 1; else hi = mid; }
    g_goff[g] = lo;
}

// ---------------- lin0: x = relu(nf @ W0^T + b) ----------------
__global__ void lin0_kernel(const float* __restrict__ nf, const float* __restrict__ b) {
    int warp = threadIdx.x >> 5;
    int node = blockIdx.x * 8 + warp;
    int o = threadIdx.x & 31;
    __shared__ float sf[8][FIN + 1];
    int base = blockIdx.x * 8;
    for (int idx = threadIdx.x; idx < 8 * FIN; idx += 256) {
        int nn = base + idx / FIN;
        sf[idx / FIN][idx % FIN] = (nn < NN) ? nf[(size_t)nn * FIN + idx % FIN] : 0.f;
    }
    __syncthreads();
    if (node >= NN) return;
    float acc = b[o];
#pragma unroll
    for (int i = 0; i < FIN; i++) acc = fmaf(sf[warp][i], g_w0T[i * DIM + o], acc);
    g_x[node * DIM + o] = fmaxf(acc, 0.f);
}

__global__ void zero_acc_kernel() {
    int i = blockIdx.x * 256 + threadIdx.x;
    if (i < NN * DIM) g_acc[i] = 0.f;
}

// ---- fused GEMM: per CTA of 128 edges; hw built in-smem, loop over 8 N-slabs ----
#define SM_A     0
#define SM_B     32768
#define SM_CSTG  65536
#define SM_SEF   65536           // 128 x 12 floats
#define SM_W1T   (65536 + 6144)
#define SM_B1    (65536 + 6144 + 5632)
#define SM_BIAS  100352          // 1024 floats
#define SMEM_GEMM_TOTAL 104448
#define CSTRIDE 272

__device__ __forceinline__ void mma_fp16(float* c, const uint32_t* a, uint32_t b0, uint32_t b1) {
    asm volatile(
        "mma.sync.aligned.m16n8k16.row.col.f32.f16.f16.f32 "
        "{%0,%1,%2,%3}, {%4,%5,%6,%7}, {%8,%9}, {%0,%1,%2,%3};"
        : "+f"(c[0]), "+f"(c[1]), "+f"(c[2]), "+f"(c[3])
        : "r"(a[0]), "r"(a[1]), "r"(a[2]), "r"(a[3]), "r"(b0), "r"(b1));
}

__global__ void __launch_bounds__(256) gemm_fused_kernel(const float* __restrict__ ef,
                                                         const float* __restrict__ b1) {
    extern __shared__ __align__(16) char smem[];
    uint32_t sbase = smem_u32(smem);
    float* sef   = (float*)(smem + SM_SEF);
    float* sw1t  = (float*)(smem + SM_W1T);
    float* sb1   = (float*)(smem + SM_B1);
    float* sbias = (float*)(smem + SM_BIAS);
    int tid = threadIdx.x, lane = tid & 31, wid = tid >> 5;
    int e0 = blockIdx.x * 128;

    // ---- prologue loads ----
    for (int idx = tid; idx < 128 * 11; idx += 256) {
        int r = idx / 11, i = idx % 11;
        int e = e0 + r;
        sef[r * 12 + i] = (e < NE) ? ef[(size_t)e * 11 + i] : 0.f;
    }
    for (int idx = tid; idx < 11 * HID; idx += 256) sw1t[idx] = g_w1T[idx];
    if (tid < 128) sb1[tid] = b1[tid];
#pragma unroll
    for (int l = 0; l < 4; l++) sbias[tid + l * 256] = g_b2p[tid + l * 256];
    __syncthreads();

    // ---- build A tile: hw = relu(ef @ W1^T + b1), fp16, xor-swizzled ----
#pragma unroll
    for (int ci = 0; ci < 8; ci++) {
        int cidx = tid + ci * 256;
        int row = cidx >> 4, c = cidx & 15;
        int k0 = c * 8;
        float v[8];
#pragma unroll
        for (int j = 0; j < 8; j++) v[j] = sb1[k0 + j];
#pragma unroll
        for (int i = 0; i < 11; i++) {
            float e_ = sef[row * 12 + i];
#pragma unroll
            for (int j = 0; j < 8; j++) v[j] = fmaf(e_, sw1t[i * HID + k0 + j], v[j]);
        }
        uint32_t p[4];
#pragma unroll
        for (int j = 0; j < 4; j++) {
            __half2 h = __floats2half2_rn(fmaxf(v[2 * j], 0.f), fmaxf(v[2 * j + 1], 0.f));
            p[j] = *(uint32_t*)&h;
        }
        int cs = (c & 8) | ((c ^ row) & 7);
        *(uint4*)(smem + SM_A + row * 256 + cs * 16) = make_uint4(p[0], p[1], p[2], p[3]);
    }
    __syncthreads();

    int wm = (wid & 3) * 32;
    int wn = (wid >> 2) * 64;

    for (int nb = 0; nb < 8; nb++) {
        const uint4* gB = (const uint4*)(g_w2b + (size_t)(nb * 128) * HID);
#pragma unroll
        for (int it = 0; it < 8; it++) {
            int idx = tid + it * 256;
            int row = idx >> 4, c = idx & 15;
            uint4 v = gB[idx];
            int cs = (c & 8) | ((c ^ row) & 7);
            *(uint4*)(smem + SM_B + row * 256 + cs * 16) = v;
        }
        __syncthreads();

        float acc[2][8][4];
#pragma unroll
        for (int mb = 0; mb < 2; mb++)
#pragma unroll
            for (int nbb = 0; nbb < 8; nbb++)
#pragma unroll
                for (int q = 0; q < 4; q++) acc[mb][nbb][q] = 0.f;

#pragma unroll
        for (int ks = 0; ks < 8; ks++) {
            int ck0 = ks * 2;
            uint32_t a[2][4], b[4][4];
#pragma unroll
            for (int mb = 0; mb < 2; mb++) {
                int row = wm + mb * 16 + (lane & 7) + ((lane >> 3) & 1) * 8;
                int ck = ck0 + (lane >> 4);
                int cs = (ck & 8) | ((ck ^ row) & 7);
                uint32_t addr = sbase + SM_A + row * 256 + cs * 16;
                asm volatile("ldmatrix.sync.aligned.m8n8.x4.shared.b16 {%0,%1,%2,%3}, [%4];"
                             : "=r"(a[mb][0]), "=r"(a[mb][1]), "=r"(a[mb][2]), "=r"(a[mb][3])
                             : "r"(addr));
            }
#pragma unroll
            for (int nb4 = 0; nb4 < 4; nb4++) {
                int t = lane >> 3, r = lane & 7;
                int n = wn + nb4 * 16 + r + (t >> 1) * 8;
                int ck = ck0 + (t & 1);
                int cs = (ck & 8) | ((ck ^ n) & 7);
                uint32_t addr = sbase + SM_B + n * 256 + cs * 16;
                asm volatile("ldmatrix.sync.aligned.m8n8.x4.shared.b16 {%0,%1,%2,%3}, [%4];"
                             : "=r"(b[nb4][0]), "=r"(b[nb4][1]), "=r"(b[nb4][2]), "=r"(b[nb4][3])
                             : "r"(addr));
            }
#pragma unroll
            for (int mb = 0; mb < 2; mb++)
#pragma unroll
                for (int nbb = 0; nbb < 8; nbb++)
                    mma_fp16(acc[mb][nbb], a[mb], b[nbb >> 1][(nbb & 1) * 2], b[nbb >> 1][(nbb & 1) * 2 + 1]);
        }
        __syncthreads();

        int g = lane >> 2, tg = lane & 3;
#pragma unroll
        for (int mb = 0; mb < 2; mb++)
#pragma unroll
            for (int nbb = 0; nbb < 8; nbb++) {
                int rowl = wm + mb * 16 + g;
                int nl = wn + nbb * 8 + tg * 2;
                float bb0 = sbias[nb * 128 + nl], bb1 = sbias[nb * 128 + nl + 1];
                float* c = acc[mb][nbb];
                __half2 p0 = __floats2half2_rn(c[0] + bb0, c[1] + bb1);
                __half2 p1 = __floats2half2_rn(c[2] + bb0, c[3] + bb1);
                *(uint32_t*)(smem + SM_CSTG + rowl * CSTRIDE + nl * 2) = *(uint32_t*)&p0;
                *(uint32_t*)(smem + SM_CSTG + (rowl + 8) * CSTRIDE + nl * 2) = *(uint32_t*)&p1;
            }
        __syncthreads();

        __half* dst = g_ewb + (size_t)e0 * NOUT + nb * 128;
#pragma unroll
        for (int it = 0; it < 8; it++) {
            int idx = tid + it * 256;
            int row = idx >> 4, c = idx & 15;
            uint4 v = *(const uint4*)(smem + SM_CSTG + row * CSTRIDE + c * 16);
            *(uint4*)(dst + (size_t)row * NOUT + c * 8) = v;
        }
        __syncthreads();
    }
}

// ---------------- NNConv: warp per edge, lane = output channel, [o][i] vectorized loads ----------------
__global__ void conv_kernel(const int* __restrict__ ei) {
    int e = blockIdx.x * 8 + (threadIdx.x >> 5);
    if (e >= NE) return;
    int o = threadIdx.x & 31;
    int src = ei[e];
    int dst = ei[NE + e];
    float xv = g_x[src * DIM + o];
    const uint4* w = (const uint4*)(g_ewb + (size_t)e * NOUT + o * 32);
    uint4 w0 = w[0], w1 = w[1], w2 = w[2], w3 = w[3];
    uint32_t ws[16] = {w0.x, w0.y, w0.z, w0.w, w1.x, w1.y, w1.z, w1.w,
                       w2.x, w2.y, w2.z, w2.w, w3.x, w3.y, w3.z, w3.w};
    float acc = 0.f;
#pragma unroll
    for (int i = 0; i < 16; i++) {
        float2 wp = __half22float2(*(__half2*)&ws[i]);
        float x0 = __shfl_sync(0xffffffffu, xv, 2 * i);
        float x1 = __shfl_sync(0xffffffffu, xv, 2 * i + 1);
        acc = fmaf(x0, wp.x, fmaf(x1, wp.y, acc));
    }
    atomicAdd(&g_acc[dst * DIM + o], acc);
}

// ---------------- scatter-mean + relu + GRU (in-place on g_x); zeroes g_acc after read ----------------
__global__ void gru_kernel(const float* __restrict__ cbias, const float* __restrict__ bih,
                           const float* __restrict__ bhh) {
    int warp = threadIdx.x >> 5;
    int node = blockIdx.x * 8 + warp;
    int o = threadIdx.x & 31;
    __shared__ float sm[8][DIM], sh[8][DIM];
    if (node < NN) {
        int c = g_cnt[node]; if (c < 1) c = 1;
        sm[warp][o] = fmaxf(g_acc[node * DIM + o] / (float)c + cbias[o], 0.f);
        sh[warp][o] = g_x[node * DIM + o];
        g_acc[node * DIM + o] = 0.f;   // ready for next conv iteration
    }
    __syncthreads();
    if (node >= NN) return;
    float gir = bih[o], giz = bih[DIM + o], gin = bih[2 * DIM + o];
    float ghr = bhh[o], ghz = bhh[DIM + o], ghn = bhh[2 * DIM + o];
#pragma unroll
    for (int i = 0; i < DIM; i++) {
        float mi = sm[warp][i], hi = sh[warp][i];
        gir = fmaf(mi, g_wihT[i * 96 + o], gir);
        giz = fmaf(mi, g_wihT[i * 96 + DIM + o], giz);
        gin = fmaf(mi, g_wihT[i * 96 + 2 * DIM + o], gin);
        ghr = fmaf(hi, g_whhT[i * 96 + o], ghr);
        ghz = fmaf(hi, g_whhT[i * 96 + DIM + o], ghz);
        ghn = fmaf(hi, g_whhT[i * 96 + 2 * DIM + o], ghn);
    }
    float r = 1.f / (1.f + expf(-(gir + ghr)));
    float z = 1.f / (1.f + expf(-(giz + ghz)));
    float nv = tanhf(gin + r * ghn);
    g_x[node * DIM + o] = (1.f - z) * nv + z * sh[warp][o];
}

__global__ void zero_s2s_kernel() {
    int i = blockIdx.x * 256 + threadIdx.x;
    if (i < NB * DIM) { g_h2[i] = 0.f; g_c2[i] = 0.f; }
    if (i < NB * 2 * DIM) g_qstar[i] = 0.f;
}

// ---------------- Set2Set LSTM cell ----------------
__global__ void lstm_kernel(const float* __restrict__ bih, const float* __restrict__ bhh) {
    int warp = threadIdx.x >> 5;
    int b = blockIdx.x * 8 + warp;
    int o = threadIdx.x & 31;
    __shared__ float sq[8][64], shh[8][DIM];
    if (b < NB) {
        sq[warp][o]      = g_qstar[b * 64 + o];
        sq[warp][32 + o] = g_qstar[b * 64 + 32 + o];
        shh[warp][o]     = g_h2[b * DIM + o];
    }
    __syncthreads();
    if (b >= NB) return;
    float gi = bih[o] + bhh[o];
    float gf = bih[32 + o] + bhh[32 + o];
    float gg = bih[64 + o] + bhh[64 + o];
    float go = bih[96 + o] + bhh[96 + o];
#pragma unroll
    for (int i = 0; i < 64; i++) {
        float v = sq[warp][i];
        gi = fmaf(v, g_lwihT[i * 128 + o], gi);
        gf = fmaf(v, g_lwihT[i * 128 + 32 + o], gf);
        gg = fmaf(v, g_lwihT[i * 128 + 64 + o], gg);
        go = fmaf(v, g_lwihT[i * 128 + 96 + o], go);
    }
#pragma unroll
    for (int i = 0; i < DIM; i++) {
        float v = shh[warp][i];
        gi = fmaf(v, g_lwhhT[i * 128 + o], gi);
        gf = fmaf(v, g_lwhhT[i * 128 + 32 + o], gf);
        gg = fmaf(v, g_lwhhT[i * 128 + 64 + o], gg);
        go = fmaf(v, g_lwhhT[i * 128 + 96 + o], go);
    }
    float si = 1.f / (1.f + expf(-gi));
    float sf = 1.f / (1.f + expf(-gf));
    float so = 1.f / (1.f + expf(-go));
    float cc = sf * g_c2[b * DIM + o] + si * tanhf(gg);
    g_c2[b * DIM + o] = cc;
    g_h2[b * DIM + o] = so * tanhf(cc);
}

// ---------------- Set2Set attention: one block per graph ----------------
__global__ void attn_kernel() {
    int g = blockIdx.x;
    int s = g_goff[g], e = g_goff[g + 1];
    int lane = threadIdx.x & 31, w = threadIdx.x >> 5;
    __shared__ float q[DIM];
    __shared__ float red[4];
    __shared__ float sr[4][DIM];
    __shared__ float sd[4];
    if (threadIdx.x < DIM) q[threadIdx.x] = g_h2[g * DIM + threadIdx.x];
    __syncthreads();
    float mx = -INFINITY;
    for (int n = s + w; n < e; n += 4) {
        float v = g_x[n * DIM + lane] * q[lane];
#pragma unroll
        for (int off = 16; off; off >>= 1) v += __shfl_xor_sync(0xffffffffu, v, off);
        mx = fmaxf(mx, v);
    }
    if (lane == 0) red[w] = mx;
    __syncthreads();
    mx = fmaxf(fmaxf(red[0], red[1]), fmaxf(red[2], red[3]));
    float denom = 0.f, racc = 0.f;
    for (int n = s + w; n < e; n += 4) {
        float xo = g_x[n * DIM + lane];
        float v = xo * q[lane];
#pragma unroll
        for (int off = 16; off; off >>= 1) v += __shfl_xor_sync(0xffffffffu, v, off);
        float ex = __expf(v - mx);
        denom += ex;
        racc = fmaf(ex, xo, racc);
    }
    sr[w][lane] = racc;
    if (lane == 0) sd[w] = denom;
    __syncthreads();
    if (w == 0) {
        float r = sr[0][lane] + sr[1][lane] + sr[2][lane] + sr[3][lane];
        float d = sd[0] + sd[1] + sd[2] + sd[3];
        r = (d > 0.f) ? r / d : 0.f;
        g_qstar[g * 64 + lane] = q[lane];
        g_qstar[g * 64 + 32 + lane] = r;
    }
}

// ---------------- writeout: [pooled (2000x64), out (100000x32)] ----------------
__global__ void writeout_kernel(float* __restrict__ out) {
    int i = blockIdx.x * 256 + threadIdx.x;
    if (i >= NB * 64 + NN * DIM) return;
    out[i] = (i < NB * 64) ? g_qstar[i] : g_x[i - NB * 64];
}

// ---------------- launch ----------------
extern "C" void kernel_launch(void* const* d_in, const int* in_sizes, int n_in,
                              void* d_out, int out_size) {
    const float* nf        = (const float*)d_in[0];
    const float* ef        = (const float*)d_in[1];
    const float* lin0_w    = (const float*)d_in[2];
    const float* lin0_b    = (const float*)d_in[3];
    const float* nn_w1     = (const float*)d_in[4];
    const float* nn_b1     = (const float*)d_in[5];
    const float* nn_w2     = (const float*)d_in[6];
    const float* nn_b2     = (const float*)d_in[7];
    const float* conv_bias = (const float*)d_in[8];
    const float* gru_wih   = (const float*)d_in[9];
    const float* gru_whh   = (const float*)d_in[10];
    const float* gru_bih   = (const float*)d_in[11];
    const float* gru_bhh   = (const float*)d_in[12];
    const float* lstm_wih  = (const float*)d_in[13];
    const float* lstm_whh  = (const float*)d_in[14];
    const float* lstm_bih  = (const float*)d_in[15];
    const float* lstm_bhh  = (const float*)d_in[16];
    const int*   ei        = (const int*)d_in[17];
    const int*   gidx      = (const int*)d_in[18];

    static int smem_set = 0;
    if (!smem_set) {
        cudaFuncSetAttribute(gemm_fused_kernel, cudaFuncAttributeMaxDynamicSharedMemorySize,
                             SMEM_GEMM_TOTAL);
        smem_set = 1;
    }

    // gemm is our 4th launch: with the harness's ~2 process-level launches ahead of
    // kernel_launch, ncu -s 5 -c 1 should capture it.
    prep_kernel<<<512, 256>>>(lin0_w, nn_w1, gru_wih, gru_whh, lstm_wih, lstm_whh, nn_w2, nn_b2);
    zero_cnt_kernel<<<(NN + 255) / 256, 256>>>();
    deg_kernel<<<(NE + 255) / 256, 256>>>(ei);
    gemm_fused_kernel<<<MPAD / 128, 256, SMEM_GEMM_TOTAL>>>(ef, nn_b1);
    lin0_kernel<<<NN / 8, 256>>>(nf, lin0_b);
    zero_acc_kernel<<<(NN * DIM + 255) / 256, 256>>>();
    goff_kernel<<<8, 256>>>(gidx);

    for (int t = 0; t < 3; t++) {
        conv_kernel<<<NE / 8, 256>>>(ei);
        gru_kernel<<<NN / 8, 256>>>(conv_bias, gru_bih, gru_bhh);   // zeroes g_acc after read
    }

    zero_s2s_kernel<<<(NB * 2 * DIM + 255) / 256, 256>>>();
    for (int s = 0; s < 3; s++) {
        lstm_kernel<<<NB / 8, 256>>>(lstm_bih, lstm_bhh);
        attn_kernel<<<NB, 128>>>();
    }
    writeout_kernel<<<(NB * 64 + NN * DIM + 255) / 256, 256>>>((float*)d_out);
}